// round 11
// baseline (speedup 1.0000x reference)
#include <cuda_runtime.h>
#include <cuda_fp16.h>
#include <cstdint>

#define N_TOK 16384
#define C_DIM 896
#define RH_DIM 448
#define E_NUM 3
#define H_DIM 3136
#define ROUTER_TAU 2e-3f

#define BN 128
#define BK 32
#define NST 3

// ---------------- scratch ----------------
__device__ __align__(256) __half g_x16[N_TOK * C_DIM];
__device__ __align__(256) __half g_w1[C_DIM * RH_DIM];                      // [C][RH]
__device__ __align__(256) __half g_win[(size_t)E_NUM * C_DIM * H_DIM];     // [E][C][H]
__device__ __align__(256) __half g_wout[(size_t)E_NUM * H_DIM * C_DIM];    // [E][H][C]
__device__ __align__(256) __half g_hid[N_TOK * RH_DIM];
__device__ __align__(256) __half g_h[(size_t)N_TOK * H_DIM];
__device__ int g_expert[N_TOK];
__device__ int g_tok_of_rank[N_TOK];
__device__ int g_flaglist[N_TOK];
__device__ int g_cnt[E_NUM];
__device__ int g_pos[E_NUM];
__device__ int g_off[E_NUM + 1];
__device__ int g_nflag;

__device__ __forceinline__ unsigned smem_u32(const void* p) {
    return (unsigned)__cvta_generic_to_shared(p);
}

// ---------------- init ----------------
__global__ void k_init() {
    if (threadIdx.x < E_NUM) { g_cnt[threadIdx.x] = 0; g_pos[threadIdx.x] = 0; }
    if (threadIdx.x == 0) g_nflag = 0;
}

// ---------------- fp32 -> fp16 casts (2 x float4 per thread) ----------------
template <int WHICH>
__global__ void k_cast(const float4* __restrict__ src, int n4) {
    __half2* dst = (WHICH == 0) ? (__half2*)g_x16
                 : (WHICH == 1) ? (__half2*)g_w1
                 : (WHICH == 2) ? (__half2*)g_win
                                : (__half2*)g_wout;
    int i = 2 * (blockIdx.x * blockDim.x + threadIdx.x);
#pragma unroll
    for (int u = 0; u < 2; u++, i++) {
        if (i < n4) {
            float4 v = src[i];
            dst[2 * i + 0] = __floats2half2_rn(v.x, v.y);
            dst[2 * i + 1] = __floats2half2_rn(v.z, v.w);
        }
    }
}

// ---------------- fp16 GEMM, BMTx128x32 tiles, 3-stage ring, 1 barrier/slice ------------
// A smem: [BMT][32] halfs swizzled: 16B chunk c in [0,4), phys = c ^ ((row>>1)&3)
// B smem: [32][128] halfs swizzled: 16B chunk c in [0,16), phys = c ^ (row&7)
// Warps: 2 M x 4 N; warp tile (BMT/2) x 32.
// EPI 0: router  A=g_x16   [16384,C],          B=g_w1   [C][RH],  relu -> g_hid (fp16)
// EPI 1: expert1 A=g_x16 rows via tok_of_rank, B=g_win[e][C][H],  relu -> g_h   (rank order)
// EPI 2: expert2 A=g_h     (grouped),          B=g_wout[e][H][C], +bias+residual -> out fp32
template <int EPI, int NN, int KK, int BMT>
__global__ void __launch_bounds__(256, 2) k_gemm(
    const float* __restrict__ bias0,
    const float* __restrict__ xres, float* __restrict__ outp)
{
    constexpr int KT = KK / BK;
    constexpr int MI = BMT / 32;          // m-frags per warp (warp tile = MI*16 rows)

    int e = (EPI == 0) ? 0 : blockIdx.z;
    int m_off = 0, M = N_TOK;
    if (EPI != 0) { m_off = g_off[e]; M = g_off[e + 1] - m_off; }
    int m0 = blockIdx.x * BMT;
    if (m0 >= M) return;
    int n0 = blockIdx.y * BN;

    const __half* A = ((EPI == 2) ? g_h : g_x16) + (size_t)m_off * KK;  // EPI1 ignores this base
    const __half* Bp = ((EPI == 0) ? g_w1 : (EPI == 1) ? g_win : g_wout) + (size_t)e * KK * NN;
    const float* bias = bias0 + (size_t)e * NN;
    __half* out16 = (EPI == 0) ? g_hid : g_h;

    __shared__ __half sA[NST][BMT][BK];
    __shared__ __half sB[NST][BK][BN];

    int tid = threadIdx.x, lane = tid & 31, warp = tid >> 5;
    int wm = warp & 1, wn = warp >> 1;  // 2 M-warps x 4 N-warps

    float acc[MI][4][4];
#pragma unroll
    for (int i = 0; i < MI; i++)
#pragma unroll
        for (int j = 0; j < 4; j++)
#pragma unroll
            for (int k = 0; k < 4; k++) acc[i][j][k] = 0.f;

    unsigned aBase0 = smem_u32(&sA[0][0][0]);
    unsigned bBase0 = smem_u32(&sB[0][0][0]);

    auto load_tile = [&](int kt, int s) {
        int k0 = kt * BK;
        unsigned aS = aBase0 + s * (BMT * BK * 2);
        unsigned bS = bBase0 + s * (BK * BN * 2);
#pragma unroll
        for (int i = 0; i < BMT / 64; i++) {  // A: BMT rows x 4 chunks
            int q = tid + i * 256;
            int row = q >> 2, c = q & 3;
            int gm = m0 + row;
            const __half* src;
            if (EPI == 1) {
                int tok = (gm < M) ? g_tok_of_rank[m_off + gm] : 0;
                src = g_x16 + (size_t)tok * KK + k0 + c * 8;
            } else {
                src = A + (size_t)(gm < M ? gm : 0) * KK + k0 + c * 8;
            }
            unsigned dst = aS + row * 64 + ((c ^ ((row >> 1) & 3)) << 4);
            int sz = (gm < M) ? 16 : 0;
            asm volatile("cp.async.cg.shared.global [%0],[%1],16,%2;\n" ::"r"(dst), "l"(src), "r"(sz));
        }
#pragma unroll
        for (int i = 0; i < 2; i++) {  // B: 32 rows x 16 chunks = 512 writes
            int q = tid + i * 256;
            int row = q >> 4, c = q & 15;
            int gn = n0 + c * 8;
            const __half* src = Bp + (size_t)(k0 + row) * NN + (gn < NN ? gn : NN - 8);
            unsigned dst = bS + row * 256 + ((c ^ (row & 7)) << 4);
            int sz = (gn < NN) ? 16 : 0;
            asm volatile("cp.async.cg.shared.global [%0],[%1],16,%2;\n" ::"r"(dst), "l"(src), "r"(sz));
        }
        asm volatile("cp.async.commit_group;\n");
    };

    auto compute_stage = [&](int s) {
        unsigned aS = aBase0 + s * (BMT * BK * 2);
        unsigned bS = bBase0 + s * (BK * BN * 2);
        int lrow = lane & 15, lsel = lane >> 4;
#pragma unroll
        for (int ks = 0; ks < 2; ks++) {
            unsigned a[MI][4], b[2][4];
#pragma unroll
            for (int mi = 0; mi < MI; mi++) {
                int r = wm * (BMT / 2) + mi * 16 + lrow;
                int c = ks * 2 + lsel;
                unsigned addr = aS + r * 64 + ((c ^ ((r >> 1) & 3)) << 4);
                asm volatile("ldmatrix.sync.aligned.m8n8.x4.shared.b16 {%0,%1,%2,%3},[%4];\n"
                             : "=r"(a[mi][0]), "=r"(a[mi][1]), "=r"(a[mi][2]), "=r"(a[mi][3])
                             : "r"(addr));
            }
#pragma unroll
            for (int nq = 0; nq < 2; nq++) {
                int r = ks * 16 + lrow;
                int c = wn * 4 + nq * 2 + lsel;
                unsigned addr = bS + r * 256 + ((c ^ (r & 7)) << 4);
                asm volatile("ldmatrix.sync.aligned.m8n8.x4.trans.shared.b16 {%0,%1,%2,%3},[%4];\n"
                             : "=r"(b[nq][0]), "=r"(b[nq][1]), "=r"(b[nq][2]), "=r"(b[nq][3])
                             : "r"(addr));
            }
#pragma unroll
            for (int mi = 0; mi < MI; mi++)
#pragma unroll
                for (int ni = 0; ni < 4; ni++) {
                    unsigned b0 = b[ni >> 1][(ni & 1) * 2], b1 = b[ni >> 1][(ni & 1) * 2 + 1];
                    asm volatile(
                        "mma.sync.aligned.m16n8k16.row.col.f32.f16.f16.f32 "
                        "{%0,%1,%2,%3},{%4,%5,%6,%7},{%8,%9},{%0,%1,%2,%3};\n"
                        : "+f"(acc[mi][ni][0]), "+f"(acc[mi][ni][1]),
                          "+f"(acc[mi][ni][2]), "+f"(acc[mi][ni][3])
                        : "r"(a[mi][0]), "r"(a[mi][1]), "r"(a[mi][2]), "r"(a[mi][3]),
                          "r"(b0), "r"(b1));
                }
        }
    };

    // 3-stage ring, single barrier per K-slice
    load_tile(0, 0);
    load_tile(1, 1);
    for (int kt = 0; kt < KT; kt++) {
        if (kt + 1 < KT) asm volatile("cp.async.wait_group 1;\n");
        else             asm volatile("cp.async.wait_group 0;\n");
        __syncthreads();
        if (kt + 2 < KT) load_tile(kt + 2, (kt + 2) % NST);
        compute_stage(kt % NST);
    }

    // ---- epilogue ----
#pragma unroll
    for (int mi = 0; mi < MI; mi++)
#pragma unroll
        for (int ni = 0; ni < 4; ni++) {
            int r0 = wm * (BMT / 2) + mi * 16 + (lane >> 2);
            int c = n0 + wn * 32 + ni * 8 + (lane & 3) * 2;
            if (c >= NN) continue;
#pragma unroll
            for (int rr = 0; rr < 2; rr++) {
                int m = m0 + r0 + rr * 8;
                if (m >= M) continue;
                float v0 = acc[mi][ni][rr * 2 + 0] + bias[c];
                float v1 = acc[mi][ni][rr * 2 + 1] + bias[c + 1];
                if (EPI <= 1) {
                    v0 = fmaxf(v0, 0.f);
                    v1 = fmaxf(v1, 0.f);
                    *reinterpret_cast<__half2*>(out16 + (size_t)(m_off + m) * NN + c) =
                        __floats2half2_rn(v0, v1);
                } else {
                    int t = g_tok_of_rank[m_off + m];
                    float2 xv = *reinterpret_cast<const float2*>(xres + (size_t)t * C_DIM + c);
                    float2 o;
                    o.x = xv.x + v0;
                    o.y = xv.y + v1;
                    *reinterpret_cast<float2*>(outp + (size_t)t * C_DIM + c) = o;
                }
            }
        }
}

// ---------------- logits + argmax + flagging + count ----------------
__global__ void k_logits(const float* __restrict__ rw2, const float* __restrict__ rb2) {
    int t = blockIdx.x * (blockDim.x >> 5) + (threadIdx.x >> 5);
    if (t >= N_TOK) return;
    int lane = threadIdx.x & 31;
    float s0 = 0.f, s1 = 0.f, s2 = 0.f;
    for (int j = lane; j < RH_DIM; j += 32) {
        float h = __half2float(g_hid[(size_t)t * RH_DIM + j]);
        s0 += h * rw2[j * 3 + 0];
        s1 += h * rw2[j * 3 + 1];
        s2 += h * rw2[j * 3 + 2];
    }
#pragma unroll
    for (int o = 16; o; o >>= 1) {
        s0 += __shfl_xor_sync(0xFFFFFFFFu, s0, o);
        s1 += __shfl_xor_sync(0xFFFFFFFFu, s1, o);
        s2 += __shfl_xor_sync(0xFFFFFFFFu, s2, o);
    }
    if (lane == 0) {
        s0 += rb2[0]; s1 += rb2[1]; s2 += rb2[2];
        int be = 0;
        float bv = s0, sv = -1e30f;
        if (s1 > bv) { sv = bv; bv = s1; be = 1; } else sv = s1;
        if (s2 > bv) { sv = bv; bv = s2; be = 2; } else if (s2 > sv) sv = s2;
        g_expert[t] = be;
        atomicAdd(&g_cnt[be], 1);
        if (bv - sv < ROUTER_TAU) {
            int i = atomicAdd(&g_nflag, 1);
            g_flaglist[i] = t;
        }
    }
}

// ---------------- fp32 exact router recompute for flagged tokens ----------------
__global__ void __launch_bounds__(RH_DIM) k_fixup(
    const float* __restrict__ x, const float* __restrict__ rw1, const float* __restrict__ rb1,
    const float* __restrict__ rw2, const float* __restrict__ rb2)
{
    __shared__ float sx[C_DIM];
    __shared__ float sh[RH_DIM];
    __shared__ float sl[3];
    int nflag = g_nflag;
    for (int it = blockIdx.x; it < nflag; it += gridDim.x) {
        int t = g_flaglist[it];
        __syncthreads();
        for (int c = threadIdx.x; c < C_DIM; c += RH_DIM) sx[c] = x[(size_t)t * C_DIM + c];
        __syncthreads();
        int j = threadIdx.x;
        float h = rb1[j];
        for (int c = 0; c < C_DIM; c++) h = fmaf(sx[c], rw1[c * RH_DIM + j], h);
        sh[j] = fmaxf(h, 0.f);
        __syncthreads();
        if (threadIdx.x < 3) {
            int ee = threadIdx.x;
            float s = rb2[ee];
            for (int jj = 0; jj < RH_DIM; jj++) s = fmaf(sh[jj], rw2[jj * 3 + ee], s);
            sl[ee] = s;
        }
        __syncthreads();
        if (threadIdx.x == 0) {
            int be = 0;
            float bv = sl[0];
            if (sl[1] > bv) { bv = sl[1]; be = 1; }
            if (sl[2] > bv) { bv = sl[2]; be = 2; }
            int old = g_expert[t];
            if (be != old) {
                g_expert[t] = be;
                atomicSub(&g_cnt[old], 1);
                atomicAdd(&g_cnt[be], 1);
            }
        }
    }
}

// ---------------- routing bookkeeping ----------------
__global__ void k_offsets() {
    if (threadIdx.x == 0) {
        g_off[0] = 0;
        for (int e = 0; e < E_NUM; e++) g_off[e + 1] = g_off[e] + g_cnt[e];
    }
}
__global__ void k_rank() {
    int t = blockIdx.x * blockDim.x + threadIdx.x;
    if (t < N_TOK) {
        int e = g_expert[t];
        int r = atomicAdd(&g_pos[e], 1);
        g_tok_of_rank[g_off[e] + r] = t;
    }
}

// ---------------- launch ----------------
extern "C" void kernel_launch(void* const* d_in, const int* in_sizes, int n_in,
                              void* d_out, int out_size) {
    const float* x = (const float*)d_in[0];
    const float* rw1 = (const float*)d_in[1];
    const float* rb1 = (const float*)d_in[2];
    const float* rw2 = (const float*)d_in[3];
    const float* rb2 = (const float*)d_in[4];
    const float* ew_in = (const float*)d_in[5];
    const float* eb_in = (const float*)d_in[6];
    const float* ew_out = (const float*)d_in[7];
    const float* eb_out = (const float*)d_in[8];
    float* out = (float*)d_out;

    k_init<<<1, 32>>>();

    int n4x = N_TOK * C_DIM / 4;
    k_cast<0><<<(n4x / 2 + 255) / 256, 256>>>((const float4*)x, n4x);
    int n4w1 = C_DIM * RH_DIM / 4;
    k_cast<1><<<(n4w1 / 2 + 255) / 256, 256>>>((const float4*)rw1, n4w1);
    int n4wi = E_NUM * C_DIM * H_DIM / 4;
    k_cast<2><<<(n4wi / 2 + 255) / 256, 256>>>((const float4*)ew_in, n4wi);
    k_cast<3><<<(n4wi / 2 + 255) / 256, 256>>>((const float4*)ew_out, n4wi);

    // router: g_hid = relu(x @ rw1 + rb1)
    dim3 g1(N_TOK / 128, (RH_DIM + BN - 1) / BN, 1);
    k_gemm<0, RH_DIM, C_DIM, 128><<<g1, 256>>>(rb1, nullptr, nullptr);

    k_logits<<<N_TOK / 8, 256>>>(rw2, rb2);
    k_fixup<<<256, RH_DIM>>>(x, rw1, rb1, rw2, rb2);
    k_offsets<<<1, 32>>>();
    k_rank<<<N_TOK / 256, 256>>>();

    // expert GEMM1 (gathers A rows via tok_of_rank): g_h = relu(x16[tok] @ ew_in[e] + eb_in[e])
    dim3 g2(N_TOK / 128, (H_DIM + BN - 1) / BN, E_NUM);
    k_gemm<1, H_DIM, C_DIM, 128><<<g2, 256>>>(eb_in, nullptr, nullptr);

    // expert GEMM2 + residual scatter: BM=64 to fix wave quantization (7 n-tiles only)
    dim3 g3(N_TOK / 64, (C_DIM + BN - 1) / BN, E_NUM);
    k_gemm<2, C_DIM, H_DIM, 64><<<g3, 256>>>(eb_out, x, out);

    (void)in_sizes; (void)n_in; (void)out_size;
}

// round 13
// speedup vs baseline: 1.0558x; 1.0558x over previous
#include <cuda_runtime.h>
#include <cuda_fp16.h>
#include <cstdint>

#define N_TOK 16384
#define C_DIM 896
#define RH_DIM 448
#define E_NUM 3
#define H_DIM 3136
#define ROUTER_TAU 2e-3f

#define BN 128
#define BK 32
#define NST 3

// cast region boundaries in float4 units
#define N4_X    (N_TOK * C_DIM / 4)                       // 3670016
#define N4_E0   N4_X
#define N4_E1   (N4_E0 + C_DIM * RH_DIM / 4)              // +100352
#define N4_E2   (N4_E1 + E_NUM * C_DIM * H_DIM / 4)       // +2107392
#define N4_E3   (N4_E2 + E_NUM * C_DIM * H_DIM / 4)       // +2107392

// ---------------- scratch ----------------
__device__ __align__(256) __half g_x16[N_TOK * C_DIM];
__device__ __align__(256) __half g_w1[C_DIM * RH_DIM];                      // [C][RH]
__device__ __align__(256) __half g_win[(size_t)E_NUM * C_DIM * H_DIM];     // [E][C][H]
__device__ __align__(256) __half g_wout[(size_t)E_NUM * H_DIM * C_DIM];    // [E][H][C]
__device__ __align__(256) __half g_hid[N_TOK * RH_DIM];
__device__ __align__(256) __half g_h[(size_t)N_TOK * H_DIM];
__device__ int g_expert[N_TOK];
__device__ int g_tok_of_rank[N_TOK];
__device__ int g_flaglist[N_TOK];
__device__ int g_cnt[E_NUM];
__device__ int g_pos[E_NUM];
__device__ int g_nflag;

__device__ __forceinline__ unsigned smem_u32(const void* p) {
    return (unsigned)__cvta_generic_to_shared(p);
}

// ---------------- fused init + all fp32->fp16 casts (2 x float4 per thread) --------------
__global__ void k_cast_all(const float4* __restrict__ x, const float4* __restrict__ rw1,
                           const float4* __restrict__ ew_in, const float4* __restrict__ ew_out) {
    if (blockIdx.x == 0 && threadIdx.x < 32) {
        if (threadIdx.x < E_NUM) { g_cnt[threadIdx.x] = 0; g_pos[threadIdx.x] = 0; }
        if (threadIdx.x == 0) g_nflag = 0;
    }
    int i = 2 * (blockIdx.x * blockDim.x + threadIdx.x);
#pragma unroll
    for (int u = 0; u < 2; u++, i++) {
        if (i >= N4_E3) return;
        const float4* src;
        __half2* dst;
        int j;
        if (i < N4_E0)      { src = x;      j = i;          dst = (__half2*)g_x16; }
        else if (i < N4_E1) { src = rw1;    j = i - N4_E0;  dst = (__half2*)g_w1; }
        else if (i < N4_E2) { src = ew_in;  j = i - N4_E1;  dst = (__half2*)g_win; }
        else                { src = ew_out; j = i - N4_E2;  dst = (__half2*)g_wout; }
        float4 v = src[j];
        dst[2 * j + 0] = __floats2half2_rn(v.x, v.y);
        dst[2 * j + 1] = __floats2half2_rn(v.z, v.w);
    }
}

// ---------------- fp16 GEMM, BMTx128x32 tiles, 3-stage ring, 1 barrier/slice ------------
// A smem: [BMT][32] halfs swizzled: 16B chunk c in [0,4), phys = c ^ ((row>>1)&3)
// B smem: [32][128] halfs swizzled: 16B chunk c in [0,16), phys = c ^ (row&7)
// Warps: 2 M x 4 N; warp tile (BMT/2) x 32.
// EPI 0: router  A=g_x16   [16384,C],          B=g_w1   [C][RH],  relu -> g_hid (fp16)
// EPI 1: expert1 A=g_x16 rows via tok_of_rank, B=g_win[e][C][H],  relu -> g_h   (rank order)
// EPI 2: expert2 A=g_h     (grouped),          B=g_wout[e][H][C], +bias+residual -> out fp32
template <int EPI, int NN, int KK, int BMT>
__global__ void __launch_bounds__(256, 2) k_gemm(
    const float* __restrict__ bias0,
    const float* __restrict__ xres, float* __restrict__ outp)
{
    constexpr int KT = KK / BK;
    constexpr int MI = BMT / 32;

    int e = (EPI == 0) ? 0 : blockIdx.z;
    int m_off = 0, M = N_TOK;
    if (EPI != 0) {
        int c0 = g_cnt[0], c1 = g_cnt[1];
        int off0 = 0, off1 = c0, off2 = c0 + c1;
        m_off = (e == 0) ? off0 : (e == 1) ? off1 : off2;
        M = (e == 0) ? c0 : (e == 1) ? c1 : (N_TOK - off2);
    }
    int m0 = blockIdx.x * BMT;
    if (m0 >= M) return;
    int n0 = blockIdx.y * BN;

    const __half* A = ((EPI == 2) ? g_h : g_x16) + (size_t)m_off * KK;  // EPI1 ignores this base
    const __half* Bp = ((EPI == 0) ? g_w1 : (EPI == 1) ? g_win : g_wout) + (size_t)e * KK * NN;
    const float* bias = bias0 + (size_t)e * NN;
    __half* out16 = (EPI == 0) ? g_hid : g_h;

    __shared__ __half sA[NST][BMT][BK];
    __shared__ __half sB[NST][BK][BN];

    int tid = threadIdx.x, lane = tid & 31, warp = tid >> 5;
    int wm = warp & 1, wn = warp >> 1;

    float acc[MI][4][4];
#pragma unroll
    for (int i = 0; i < MI; i++)
#pragma unroll
        for (int j = 0; j < 4; j++)
#pragma unroll
            for (int k = 0; k < 4; k++) acc[i][j][k] = 0.f;

    unsigned aBase0 = smem_u32(&sA[0][0][0]);
    unsigned bBase0 = smem_u32(&sB[0][0][0]);

    auto load_tile = [&](int kt, int s) {
        int k0 = kt * BK;
        unsigned aS = aBase0 + s * (BMT * BK * 2);
        unsigned bS = bBase0 + s * (BK * BN * 2);
#pragma unroll
        for (int i = 0; i < BMT / 64; i++) {
            int q = tid + i * 256;
            int row = q >> 2, c = q & 3;
            int gm = m0 + row;
            const __half* src;
            if (EPI == 1) {
                int tok = (gm < M) ? g_tok_of_rank[m_off + gm] : 0;
                src = g_x16 + (size_t)tok * KK + k0 + c * 8;
            } else {
                src = A + (size_t)(gm < M ? gm : 0) * KK + k0 + c * 8;
            }
            unsigned dst = aS + row * 64 + ((c ^ ((row >> 1) & 3)) << 4);
            int sz = (gm < M) ? 16 : 0;
            asm volatile("cp.async.cg.shared.global [%0],[%1],16,%2;\n" ::"r"(dst), "l"(src), "r"(sz));
        }
#pragma unroll
        for (int i = 0; i < 2; i++) {
            int q = tid + i * 256;
            int row = q >> 4, c = q & 15;
            int gn = n0 + c * 8;
            const __half* src = Bp + (size_t)(k0 + row) * NN + (gn < NN ? gn : NN - 8);
            unsigned dst = bS + row * 256 + ((c ^ (row & 7)) << 4);
            int sz = (gn < NN) ? 16 : 0;
            asm volatile("cp.async.cg.shared.global [%0],[%1],16,%2;\n" ::"r"(dst), "l"(src), "r"(sz));
        }
        asm volatile("cp.async.commit_group;\n");
    };

    auto compute_stage = [&](int s) {
        unsigned aS = aBase0 + s * (BMT * BK * 2);
        unsigned bS = bBase0 + s * (BK * BN * 2);
        int lrow = lane & 15, lsel = lane >> 4;
#pragma unroll
        for (int ks = 0; ks < 2; ks++) {
            unsigned a[MI][4], b[2][4];
#pragma unroll
            for (int mi = 0; mi < MI; mi++) {
                int r = wm * (BMT / 2) + mi * 16 + lrow;
                int c = ks * 2 + lsel;
                unsigned addr = aS + r * 64 + ((c ^ ((r >> 1) & 3)) << 4);
                asm volatile("ldmatrix.sync.aligned.m8n8.x4.shared.b16 {%0,%1,%2,%3},[%4];\n"
                             : "=r"(a[mi][0]), "=r"(a[mi][1]), "=r"(a[mi][2]), "=r"(a[mi][3])
                             : "r"(addr));
            }
#pragma unroll
            for (int nq = 0; nq < 2; nq++) {
                int r = ks * 16 + lrow;
                int c = wn * 4 + nq * 2 + lsel;
                unsigned addr = bS + r * 256 + ((c ^ (r & 7)) << 4);
                asm volatile("ldmatrix.sync.aligned.m8n8.x4.trans.shared.b16 {%0,%1,%2,%3},[%4];\n"
                             : "=r"(b[nq][0]), "=r"(b[nq][1]), "=r"(b[nq][2]), "=r"(b[nq][3])
                             : "r"(addr));
            }
#pragma unroll
            for (int mi = 0; mi < MI; mi++)
#pragma unroll
                for (int ni = 0; ni < 4; ni++) {
                    unsigned b0 = b[ni >> 1][(ni & 1) * 2], b1 = b[ni >> 1][(ni & 1) * 2 + 1];
                    asm volatile(
                        "mma.sync.aligned.m16n8k16.row.col.f32.f16.f16.f32 "
                        "{%0,%1,%2,%3},{%4,%5,%6,%7},{%8,%9},{%0,%1,%2,%3};\n"
                        : "+f"(acc[mi][ni][0]), "+f"(acc[mi][ni][1]),
                          "+f"(acc[mi][ni][2]), "+f"(acc[mi][ni][3])
                        : "r"(a[mi][0]), "r"(a[mi][1]), "r"(a[mi][2]), "r"(a[mi][3]),
                          "r"(b0), "r"(b1));
                }
        }
    };

    load_tile(0, 0);
    load_tile(1, 1);
    for (int kt = 0; kt < KT; kt++) {
        if (kt + 1 < KT) asm volatile("cp.async.wait_group 1;\n");
        else             asm volatile("cp.async.wait_group 0;\n");
        __syncthreads();
        if (kt + 2 < KT) load_tile(kt + 2, (kt + 2) % NST);
        compute_stage(kt % NST);
    }

    // ---- epilogue ----
#pragma unroll
    for (int mi = 0; mi < MI; mi++)
#pragma unroll
        for (int ni = 0; ni < 4; ni++) {
            int r0 = wm * (BMT / 2) + mi * 16 + (lane >> 2);
            int c = n0 + wn * 32 + ni * 8 + (lane & 3) * 2;
            if (c >= NN) continue;
#pragma unroll
            for (int rr = 0; rr < 2; rr++) {
                int m = m0 + r0 + rr * 8;
                if (m >= M) continue;
                float v0 = acc[mi][ni][rr * 2 + 0] + bias[c];
                float v1 = acc[mi][ni][rr * 2 + 1] + bias[c + 1];
                if (EPI <= 1) {
                    v0 = fmaxf(v0, 0.f);
                    v1 = fmaxf(v1, 0.f);
                    *reinterpret_cast<__half2*>(out16 + (size_t)(m_off + m) * NN + c) =
                        __floats2half2_rn(v0, v1);
                } else {
                    int t = g_tok_of_rank[m_off + m];
                    float2 xv = *reinterpret_cast<const float2*>(xres + (size_t)t * C_DIM + c);
                    float2 o;
                    o.x = xv.x + v0;
                    o.y = xv.y + v1;
                    *reinterpret_cast<float2*>(outp + (size_t)t * C_DIM + c) = o;
                }
            }
        }
}

// ---------------- logits + argmax + flagging + count ----------------
__global__ void k_logits(const float* __restrict__ rw2, const float* __restrict__ rb2) {
    int t = blockIdx.x * (blockDim.x >> 5) + (threadIdx.x >> 5);
    if (t >= N_TOK) return;
    int lane = threadIdx.x & 31;
    float s0 = 0.f, s1 = 0.f, s2 = 0.f;
    for (int j = lane; j < RH_DIM; j += 32) {
        float h = __half2float(g_hid[(size_t)t * RH_DIM + j]);
        s0 += h * rw2[j * 3 + 0];
        s1 += h * rw2[j * 3 + 1];
        s2 += h * rw2[j * 3 + 2];
    }
#pragma unroll
    for (int o = 16; o; o >>= 1) {
        s0 += __shfl_xor_sync(0xFFFFFFFFu, s0, o);
        s1 += __shfl_xor_sync(0xFFFFFFFFu, s1, o);
        s2 += __shfl_xor_sync(0xFFFFFFFFu, s2, o);
    }
    if (lane == 0) {
        s0 += rb2[0]; s1 += rb2[1]; s2 += rb2[2];
        int be = 0;
        float bv = s0, sv = -1e30f;
        if (s1 > bv) { sv = bv; bv = s1; be = 1; } else sv = s1;
        if (s2 > bv) { sv = bv; bv = s2; be = 2; } else if (s2 > sv) sv = s2;
        g_expert[t] = be;
        atomicAdd(&g_cnt[be], 1);
        if (bv - sv < ROUTER_TAU) {
            int i = atomicAdd(&g_nflag, 1);
            g_flaglist[i] = t;
        }
    }
}

// ---------------- fp32 exact router recompute for flagged tokens ----------------
__global__ void __launch_bounds__(RH_DIM) k_fixup(
    const float* __restrict__ x, const float* __restrict__ rw1, const float* __restrict__ rb1,
    const float* __restrict__ rw2, const float* __restrict__ rb2)
{
    __shared__ float sx[C_DIM];
    __shared__ float sh[RH_DIM];
    __shared__ float sl[3];
    int nflag = g_nflag;
    for (int it = blockIdx.x; it < nflag; it += gridDim.x) {
        int t = g_flaglist[it];
        __syncthreads();
        for (int c = threadIdx.x; c < C_DIM; c += RH_DIM) sx[c] = x[(size_t)t * C_DIM + c];
        __syncthreads();
        int j = threadIdx.x;
        float h = rb1[j];
        for (int c = 0; c < C_DIM; c++) h = fmaf(sx[c], rw1[c * RH_DIM + j], h);
        sh[j] = fmaxf(h, 0.f);
        __syncthreads();
        if (threadIdx.x < 3) {
            int ee = threadIdx.x;
            float s = rb2[ee];
            for (int jj = 0; jj < RH_DIM; jj++) s = fmaf(sh[jj], rw2[jj * 3 + ee], s);
            sl[ee] = s;
        }
        __syncthreads();
        if (threadIdx.x == 0) {
            int be = 0;
            float bv = sl[0];
            if (sl[1] > bv) { bv = sl[1]; be = 1; }
            if (sl[2] > bv) { bv = sl[2]; be = 2; }
            int old = g_expert[t];
            if (be != old) {
                g_expert[t] = be;
                atomicSub(&g_cnt[old], 1);
                atomicAdd(&g_cnt[be], 1);
            }
        }
    }
}

// ---------------- rank (computes offsets locally from final g_cnt) ----------------
__global__ void k_rank() {
    int t = blockIdx.x * blockDim.x + threadIdx.x;
    if (t < N_TOK) {
        int c0 = g_cnt[0], c1 = g_cnt[1];
        int e = g_expert[t];
        int off = (e == 0) ? 0 : (e == 1) ? c0 : (c0 + c1);
        int r = atomicAdd(&g_pos[e], 1);
        g_tok_of_rank[off + r] = t;
    }
}

// ---------------- launch ----------------
extern "C" void kernel_launch(void* const* d_in, const int* in_sizes, int n_in,
                              void* d_out, int out_size) {
    const float* x = (const float*)d_in[0];
    const float* rw1 = (const float*)d_in[1];
    const float* rb1 = (const float*)d_in[2];
    const float* rw2 = (const float*)d_in[3];
    const float* rb2 = (const float*)d_in[4];
    const float* ew_in = (const float*)d_in[5];
    const float* eb_in = (const float*)d_in[6];
    const float* ew_out = (const float*)d_in[7];
    const float* eb_out = (const float*)d_in[8];
    float* out = (float*)d_out;

    // fused init + casts: N4_E3 float4s, 2 per thread
    int nthreads = (N4_E3 + 1) / 2;
    k_cast_all<<<(nthreads + 255) / 256, 256>>>((const float4*)x, (const float4*)rw1,
                                                (const float4*)ew_in, (const float4*)ew_out);

    // router: g_hid = relu(x @ rw1 + rb1)
    dim3 g1(N_TOK / 128, (RH_DIM + BN - 1) / BN, 1);
    k_gemm<0, RH_DIM, C_DIM, 128><<<g1, 256>>>(rb1, nullptr, nullptr);

    k_logits<<<N_TOK / 8, 256>>>(rw2, rb2);
    k_fixup<<<256, RH_DIM>>>(x, rw1, rb1, rw2, rb2);
    k_rank<<<N_TOK / 256, 256>>>();

    // expert GEMM1 (gathers A rows via tok_of_rank): g_h = relu(x16[tok] @ ew_in[e] + eb_in[e])
    dim3 g2(N_TOK / 128, (H_DIM + BN - 1) / BN, E_NUM);
    k_gemm<1, H_DIM, C_DIM, 128><<<g2, 256>>>(eb_in, nullptr, nullptr);

    // expert GEMM2 + residual scatter (BM=128)
    dim3 g3(N_TOK / 128, (C_DIM + BN - 1) / BN, E_NUM);
    k_gemm<2, C_DIM, H_DIM, 128><<<g3, 256>>>(eb_out, x, out);

    (void)in_sizes; (void)n_in; (void)out_size;
}